// round 1
// baseline (speedup 1.0000x reference)
#include <cuda_runtime.h>

#define N_NODES 20000
#define N_EDGES 160000
#define NH 8
#define EPS 1e-12f
#define SLOPE 0.2f

// ---------------- scratch (device globals; no allocation allowed) ----------------
__device__ float g_value[N_NODES * 256];
__device__ float g_nb[N_NODES * 256];
__device__ float g_ssrc[N_NODES * NH];
__device__ float g_stgt[N_NODES * NH];
__device__ float g_gatep[N_NODES * NH];
__device__ float g_srel_dr[50 * NH];
__device__ float g_srel_da[4 * NH];
__device__ int g_deg[N_NODES];
__device__ int g_cursor[N_NODES];
__device__ int g_off[N_NODES + 1];
__device__ int g_esort[N_EDGES];
__device__ unsigned g_maxraw[2];

__device__ __forceinline__ float leaky(float x) { return x >= 0.f ? x : SLOPE * x; }

__device__ __forceinline__ float wsum(float v) {
#pragma unroll
    for (int o = 16; o; o >>= 1) v += __shfl_xor_sync(0xFFFFFFFFu, v, o);
    return v;
}

__device__ __forceinline__ unsigned encodef(float f) {
    unsigned b = __float_as_uint(f);
    return (b & 0x80000000u) ? ~b : (b | 0x80000000u);
}
__device__ __forceinline__ float decodef(unsigned u) {
    unsigned b = (u & 0x80000000u) ? (u & 0x7FFFFFFFu) : ~u;
    return __uint_as_float(b);
}

// ---------------- init ----------------
__global__ void k_init() {
    int i = blockIdx.x * blockDim.x + threadIdx.x;
    if (i < N_NODES) { g_deg[i] = 0; g_cursor[i] = 0; }
    if (i < 2) g_maxraw[i] = 0u;
}

// ---------------- relation score tables ----------------
// s_rel[e,h] = rel_inp[e] . u[h]  where u[h] = W_relation[:, h*16:(h+1)*16] @ w_rel[h]
// rel_inp = [deprel_emb[dr] | deparc_emb[da]]  -> split into two additive tables.
__global__ void k_tables(const float* __restrict__ Wrel, const float* __restrict__ wrel,
                         const float* __restrict__ dre_emb, const float* __restrict__ dae_emb) {
    __shared__ float us[NH * 128];
    int tid = threadIdx.x;  // 256 threads
    for (int id = tid; id < NH * 128; id += 256) {
        int h = id >> 7, k = id & 127;
        float s = 0.f;
#pragma unroll
        for (int j = 0; j < 16; j++) s += Wrel[k * 128 + h * 16 + j] * wrel[h * 16 + j];
        us[h * 128 + k] = s;
    }
    __syncthreads();
    for (int id = tid; id < 50 * NH; id += 256) {
        int r = id / NH, h = id % NH;
        float s = 0.f;
        for (int k = 0; k < 64; k++) s += dre_emb[r * 64 + k] * us[h * 128 + k];
        g_srel_dr[r * NH + h] = s;
    }
    for (int id = tid; id < 4 * NH; id += 256) {
        int a = id / NH, h = id % NH;
        float s = 0.f;
        for (int k = 0; k < 64; k++) s += dae_emb[a * 64 + k] * us[h * 128 + 64 + k];
        g_srel_da[a * NH + h] = s;
    }
}

// ---------------- fused node GEMM: [N,256] @ [256, 512] -> value | nb ----------------
// Classic SGEMM: BM=BN=64, BK=16, 256 threads, 4x4 per thread.
__global__ void k_gemm(const float* __restrict__ inp, const float* __restrict__ Wv,
                       const float* __restrict__ Wn, const float* __restrict__ nbias) {
    __shared__ float As[16][64];
    __shared__ float Bs[16][64];
    int row0 = blockIdx.y * 64;
    int col0 = blockIdx.x * 64;  // 0..448, cols >= 256 are neighbor_w
    int tid = threadIdx.x;

    int arow = tid >> 2, ak = (tid & 3) << 2;
    int bk = tid >> 4, bc = (tid & 15) << 2;
    const float* B = (col0 < 256) ? Wv : Wn;
    int bcol = (col0 & 255) + bc;

    int tx = tid & 15, ty = tid >> 4;
    float acc[4][4];
#pragma unroll
    for (int i = 0; i < 4; i++)
#pragma unroll
        for (int j = 0; j < 4; j++) acc[i][j] = 0.f;

    int gr = row0 + arow;
    bool avalid = gr < N_NODES;

    for (int k0 = 0; k0 < 256; k0 += 16) {
        float4 av = make_float4(0.f, 0.f, 0.f, 0.f);
        if (avalid) av = *(const float4*)(inp + gr * 256 + k0 + ak);
        As[ak + 0][arow] = av.x;
        As[ak + 1][arow] = av.y;
        As[ak + 2][arow] = av.z;
        As[ak + 3][arow] = av.w;
        float4 bv = *(const float4*)(B + (k0 + bk) * 256 + bcol);
        *(float4*)&Bs[bk][bc] = bv;
        __syncthreads();
#pragma unroll
        for (int kk = 0; kk < 16; kk++) {
            float4 a4 = *(const float4*)&As[kk][ty * 4];
            float4 b4 = *(const float4*)&Bs[kk][tx * 4];
            float ar[4] = {a4.x, a4.y, a4.z, a4.w};
            float br[4] = {b4.x, b4.y, b4.z, b4.w};
#pragma unroll
            for (int i = 0; i < 4; i++)
#pragma unroll
                for (int j = 0; j < 4; j++) acc[i][j] += ar[i] * br[j];
        }
        __syncthreads();
    }

    bool isNb = col0 >= 256;
#pragma unroll
    for (int i = 0; i < 4; i++) {
        int r = row0 + ty * 4 + i;
        if (r >= N_NODES) break;
        float4 o;
        if (isNb) {
            int cb = (col0 - 256) + tx * 4;
            o = make_float4(acc[i][0] + nbias[cb], acc[i][1] + nbias[cb + 1],
                            acc[i][2] + nbias[cb + 2], acc[i][3] + nbias[cb + 3]);
            *(float4*)(g_nb + r * 256 + cb) = o;
        } else {
            o = make_float4(acc[i][0], acc[i][1], acc[i][2], acc[i][3]);
            *(float4*)(g_value + r * 256 + col0 + tx * 4) = o;
        }
    }
}

// ---------------- per-node scalars: s_src, s_tgt, gate partial ----------------
__global__ void k_nodescal(const float* __restrict__ inp, const float* __restrict__ wsrc,
                           const float* __restrict__ wtgt, const float* __restrict__ gatew) {
    int wid = (blockIdx.x * blockDim.x + threadIdx.x) >> 5;
    int lane = threadIdx.x & 31;
    if (wid >= N_NODES) return;
    const float* vrow = g_value + wid * 256;
    const float* irow = inp + wid * 256;
    float vv[8], ii[8];
#pragma unroll
    for (int j = 0; j < 8; j++) {
        vv[j] = vrow[j * 32 + lane];
        ii[j] = irow[j * 32 + lane];
    }
#pragma unroll
    for (int h = 0; h < 8; h++) {
        float ss = wsum(vv[h] * wsrc[h * 32 + lane]);
        float st = wsum(vv[h] * wtgt[h * 32 + lane]);
        float gp = 0.f;
#pragma unroll
        for (int j = 0; j < 8; j++) gp += ii[j] * gatew[(j * 32 + lane) * 8 + h];
        gp = wsum(gp);
        if (lane == 0) {
            g_ssrc[wid * 8 + h] = ss;
            g_stgt[wid * 8 + h] = st;
            g_gatep[wid * 8 + h] = gp;
        }
    }
}

// ---------------- CSR build ----------------
__global__ void k_count(const int* __restrict__ ei) {
    int e = blockIdx.x * blockDim.x + threadIdx.x;
    if (e < N_EDGES) atomicAdd(&g_deg[ei[N_EDGES + e]], 1);
}

__global__ void k_scan() {  // single block, 1024 threads
    __shared__ int sd[1024];
    __shared__ int carry;
    int tid = threadIdx.x;
    if (tid == 0) carry = 0;
    __syncthreads();
    for (int base = 0; base < N_NODES; base += 1024) {
        int i = base + tid;
        int v = (i < N_NODES) ? g_deg[i] : 0;
        sd[tid] = v;
        __syncthreads();
        for (int o = 1; o < 1024; o <<= 1) {
            int t = (tid >= o) ? sd[tid - o] : 0;
            __syncthreads();
            sd[tid] += t;
            __syncthreads();
        }
        if (i < N_NODES) g_off[i] = carry + sd[tid] - v;
        int tot = sd[1023];
        __syncthreads();
        if (tid == 0) carry += tot;
        __syncthreads();
    }
    if (tid == 0) g_off[N_NODES] = carry;
}

__global__ void k_fill(const int* __restrict__ ei, const int* __restrict__ dre,
                       const int* __restrict__ dae) {
    int e = blockIdx.x * blockDim.x + threadIdx.x;
    if (e >= N_EDGES) return;
    int src = ei[e], tgt = ei[N_EDGES + e];
    int pos = g_off[tgt] + atomicAdd(&g_cursor[tgt], 1);
    g_esort[pos] = src | (dre[e] << 16) | (dae[e] << 22);
}

// ---------------- global score max (softmax stabilizer, matches reference exactly) ----------------
__global__ void k_max(const int* __restrict__ ei, const int* __restrict__ dre,
                      const int* __restrict__ dae) {
    int e = blockIdx.x * blockDim.x + threadIdx.x;
    float mv = -1e30f, mr = -1e30f;
    if (e < N_EDGES) {
        int src = ei[e], tgt = ei[N_EDGES + e], dr = dre[e], da = dae[e];
#pragma unroll
        for (int h = 0; h < 8; h++) {
            float st = g_stgt[tgt * 8 + h];
            float rv = g_ssrc[src * 8 + h] + st;
            float rr = g_srel_dr[dr * 8 + h] + g_srel_da[da * 8 + h] + st;
            mv = fmaxf(mv, rv);
            mr = fmaxf(mr, rr);
        }
    }
#pragma unroll
    for (int o = 16; o; o >>= 1) {
        mv = fmaxf(mv, __shfl_xor_sync(0xFFFFFFFFu, mv, o));
        mr = fmaxf(mr, __shfl_xor_sync(0xFFFFFFFFu, mr, o));
    }
    if ((threadIdx.x & 31) == 0) {
        atomicMax(&g_maxraw[0], encodef(mv));
        atomicMax(&g_maxraw[1], encodef(mr));
    }
}

// ---------------- aggregation + full epilogue: one block per target node ----------------
// warp h handles head h; lane = DV component. Single pass: numerator and denominator
// accumulated together (normalization is constant per (node, head)).
__global__ void k_agg(const float* __restrict__ fpw, const float* __restrict__ fpb,
                      const float* __restrict__ gatew, const float* __restrict__ gateb,
                      const float* __restrict__ fbias, float* __restrict__ out) {
    int n = blockIdx.x;
    int lane = threadIdx.x & 31, h = threadIdx.x >> 5;
    float Mv = leaky(decodef(g_maxraw[0]));
    float Mr = leaky(decodef(g_maxraw[1]));
    int e0 = g_off[n], e1 = g_off[n + 1];
    float stgt = g_stgt[n * 8 + h];
    float accv = 0.f, accr = 0.f, accnb = 0.f, denv = 0.f, denr = 0.f;
    for (int p = e0; p < e1; p++) {
        int pk = g_esort[p];
        int src = pk & 0xFFFF;
        int dr = (pk >> 16) & 0x3F;
        int da = (pk >> 22) & 0x3;
        float rv = g_ssrc[src * 8 + h] + stgt;
        float rr = g_srel_dr[dr * 8 + h] + g_srel_da[da * 8 + h] + stgt;
        float ev = __expf(leaky(rv) - Mv);
        float er = __expf(leaky(rr) - Mr);
        denv += ev;
        denr += er;
        float x = g_value[src * 256 + h * 32 + lane];
        float y = g_nb[src * 256 + h * 32 + lane];
        accv += ev * x;
        accr += er * x;
        accnb += y;
    }
    accv /= (denv + EPS);
    accr /= (denr + EPS);

    __shared__ float cat[8][64];
    __shared__ float nbs[256];
    cat[h][lane] = accv;
    cat[h][32 + lane] = accr;
    nbs[h * 32 + lane] = accnb / fmaxf((float)(e1 - e0), 1.f);
    __syncthreads();

    // gate = sigmoid(inp . gw[:256] + nb_agg . gw[256:] + gb)
    float gp = 0.f;
#pragma unroll
    for (int j = 0; j < 8; j++) {
        int t = j * 32 + lane;
        gp += nbs[t] * gatew[(256 + t) * 8 + h];
    }
    gp = wsum(gp);
    float gate = 1.f / (1.f + __expf(-(g_gatep[n * 8 + h] + gp + gateb[h])));

    // head_out[h, lane] = cat[h,:] @ final_proj_w[h,:,lane] + b
    float ho = fpb[h * 32 + lane];
#pragma unroll
    for (int d = 0; d < 64; d++) ho += cat[h][d] * fpw[h * 2048 + d * 32 + lane];

    out[n * 256 + h * 32 + lane] = ho * gate + fbias[h * 32 + lane];
}

// ---------------- launcher ----------------
extern "C" void kernel_launch(void* const* d_in, const int* in_sizes, int n_in,
                              void* d_out, int out_size) {
    const float* inp = (const float*)d_in[0];
    // d_in[1] dist_edge: unused by the reference
    const float* Wv = (const float*)d_in[2];
    const float* Wrel = (const float*)d_in[3];
    const float* dre_emb = (const float*)d_in[4];
    const float* dae_emb = (const float*)d_in[5];
    const float* wsrc = (const float*)d_in[6];
    const float* wtgt = (const float*)d_in[7];
    const float* wrel = (const float*)d_in[8];
    const float* fpw = (const float*)d_in[9];
    const float* fpb = (const float*)d_in[10];
    const float* Wn = (const float*)d_in[11];
    const float* nbias = (const float*)d_in[12];
    const float* gatew = (const float*)d_in[13];
    const float* gateb = (const float*)d_in[14];
    const float* fbias = (const float*)d_in[15];
    const int* ei = (const int*)d_in[16];
    const int* dre = (const int*)d_in[17];
    const int* dae = (const int*)d_in[18];
    float* out = (float*)d_out;

    k_init<<<(N_NODES + 255) / 256, 256>>>();
    k_tables<<<1, 256>>>(Wrel, wrel, dre_emb, dae_emb);
    k_gemm<<<dim3(8, 313), 256>>>(inp, Wv, Wn, nbias);
    k_nodescal<<<(N_NODES * 32 + 255) / 256, 256>>>(inp, wsrc, wtgt, gatew);
    k_count<<<(N_EDGES + 255) / 256, 256>>>(ei);
    k_scan<<<1, 1024>>>();
    k_fill<<<(N_EDGES + 255) / 256, 256>>>(ei, dre, dae);
    k_max<<<(N_EDGES + 255) / 256, 256>>>(ei, dre, dae);
    k_agg<<<N_NODES, 256>>>(fpw, fpb, gatew, gateb, fbias, out);
}